// round 7
// baseline (speedup 1.0000x reference)
#include <cuda_runtime.h>
#include <cstdint>
#include <cstddef>

// MPS chain contraction, 32768 elements, 221 steps of 3x3 matrices.
// v_out = e0^T * M_1 * ... * M_221,  M_l = bias + sum_d x[l,d] * T[l,:,:,d]
//
// Round-7: same structure as round 6 (scalar f32, 4 segments across blocks,
// depth-3 staging pipeline, transposed conflict-free smem layout) but the
// staging path is rebuilt: instead of 18x 4-byte cp.async per thread-chunk
// (LDGSTS rt=8 made this the dominant LSU cost), each thread does 6x
// LDG.128 from the ALIGNED window covering its elements' 18-float chunk,
// then scatters the in-range floats with predicated STS.32. ~2.4x fewer
// LSU cycles for the same 91 MB.

#define NSEG    4
#define BT      256
#define EPB     256            // elements per block (1 per thread)
#define NEBLK   128            // 32768 / 256
#define NBLK    (NSEG * NEBLK) // 512
#define CH      6              // steps per chunk
#define NCH     10             // chunks (covers 60 >= 56 steps)
#define ESTRIDE 693            // floats per element
#define NELEM   32768

// Transposed staging layout (bytes): buffer b at b*CHUNKB, float row f
// (0..17) at f*ROWB, element e at e*4. ROWB = 1028 -> word stride 257 == 1
// (mod 32): conflict-free linear reads, near-conflict-free scattered writes.
#define ROWB    1028
#define CHUNKB  18512
#define NBUF    3
#define TPAD    28             // floats per step in smem (27 + pad)
#define TBYTES  (56 * TPAD * 4)              // 6272
#define SMEM_BYTES (NBUF * CHUNKB + TBYTES)  // 61808 -> 3 blocks/SM

__device__ float g_vec[3 * NELEM];       // seg-0 vectors
__device__ float g_mat[3 * 9 * NELEM];   // seg 1..3 partial matrices

__device__ __forceinline__ float ldsf(uint32_t addr) {
    float v; asm("ld.shared.f32 %0, [%1];" : "=f"(v) : "r"(addr)); return v;
}
__device__ __forceinline__ void stsf(uint32_t addr, float v) {
    asm volatile("st.shared.f32 [%0], %1;" :: "r"(addr), "f"(v) : "memory");
}
__device__ __forceinline__ void lds4(float& a, float& b, float& c, float& d, uint32_t addr) {
    asm("ld.shared.v4.f32 {%0,%1,%2,%3}, [%4];"
        : "=f"(a), "=f"(b), "=f"(c), "=f"(d) : "r"(addr));
}

extern __shared__ float smem_f[];

// Stage one 18-float chunk for all 256 elements via aligned LDG.128 +
// predicated STS.32 scatter. base0 = global float index of the chunk start
// for element 0 of this block.
__device__ __forceinline__ void stage_chunk(const float* __restrict__ samples,
                                            int base0, uint32_t xb, int tid) {
    #pragma unroll
    for (int k = 0; k < 6; k++) {
        int i  = k * BT + tid;          // 0 .. 1535
        int eq = i / 6;                 // element 0..255
        int v  = i % 6;                 // vec4 slot 0..5
        int S  = base0 + eq * ESTRIDE;  // chunk start (float idx)
        int A  = S & ~3;                // aligned window start
        const float4 d = *reinterpret_cast<const float4*>(samples + A + 4 * v);
        int f0 = A + 4 * v - S;         // element-local index of d.x (-3..20)
        float vals[4] = {d.x, d.y, d.z, d.w};
        #pragma unroll
        for (int q = 0; q < 4; q++) {
            int f = f0 + q;
            if (f >= 0 && f < 18)
                stsf(xb + (uint32_t)(f * ROWB + eq * 4), vals[q]);
        }
    }
}

__global__ void __launch_bounds__(BT, 3)
mps_partial_kernel(const float* __restrict__ samples,
                   const float* __restrict__ T1,
                   const float* __restrict__ bias)
{
    const int tid  = threadIdx.x;
    const int seg  = blockIdx.x & (NSEG - 1);
    const int eblk = blockIdx.x >> 2;
    const int e0   = eblk * EPB;
    const int lbase = (seg == 0) ? 0 : (55 * seg + 1);   // 0,56,111,166
    const int len   = (seg == 0) ? 56 : 55;

    uint32_t sbase = (uint32_t)__cvta_generic_to_shared(smem_f);
    uint32_t tbase = sbase + NBUF * CHUNKB;
    float* Tsh = smem_f + (NBUF * CHUNKB) / 4;

    // Stage this segment's T: [l][m] at l*TPAD + m.
    for (int i = tid; i < len * 27; i += BT) {
        int l = i / 27, m = i % 27;
        Tsh[l * TPAD + m] = T1[(lbase + l) * 27 + m];
    }

    float Bq[9];
    #pragma unroll
    for (int j = 0; j < 9; j++) Bq[j] = bias[j];
    bool ident = true;
    #pragma unroll
    for (int i = 0; i < 3; i++)
        #pragma unroll
        for (int j = 0; j < 3; j++)
            ident &= (Bq[i * 3 + j] == ((i == j) ? 1.0f : 0.0f));

    const int base00 = e0 * ESTRIDE + 3 * lbase;   // fits 32-bit

    // Depth-3 prologue: chunks 0 and 1 staged before compute starts.
    stage_chunk(samples, base00 + 0 * (CH * 3), sbase + 0 * CHUNKB, tid);
    stage_chunk(samples, base00 + 1 * (CH * 3), sbase + 1 * CHUNKB, tid);

    // State: seg 0 -> vector in P[0..2]; segs 1-3 -> matrix in P[0..8].
    float P[9];
    #pragma unroll
    for (int j = 0; j < 9; j++) P[j] = (j % 4 == 0) ? 1.0f : 0.0f;
    if (seg == 0) { P[1] = 0.0f; P[2] = 0.0f; }   // v = (1,0,0)

    for (int c = 0; c < NCH; c++) {
        __syncthreads();   // all STS for chunk c (staged 2 iters ago) visible

        uint32_t xaddr = sbase + (uint32_t)((c % NBUF) * CHUNKB + tid * 4);
        const int nst = min(CH, len - c * CH);    // 6,...,6, then 2 (or 1)

        #pragma unroll
        for (int st = 0; st < CH; st++) {
            if (st >= nst) break;
            float x0 = ldsf(xaddr + (st * 3 + 0) * ROWB);
            float x1 = ldsf(xaddr + (st * 3 + 1) * ROWB);
            float x2 = ldsf(xaddr + (st * 3 + 2) * ROWB);
            uint32_t ta = tbase + (uint32_t)((c * CH + st) * (TPAD * 4));
            float t[28];
            lds4(t[0],  t[1],  t[2],  t[3],  ta);
            lds4(t[4],  t[5],  t[6],  t[7],  ta + 16);
            lds4(t[8],  t[9],  t[10], t[11], ta + 32);
            lds4(t[12], t[13], t[14], t[15], ta + 48);
            lds4(t[16], t[17], t[18], t[19], ta + 64);
            lds4(t[20], t[21], t[22], t[23], ta + 80);
            lds4(t[24], t[25], t[26], t[27], ta + 96);

            if (ident) {
                float S00 = fmaf(x2, t[2],  fmaf(x1, t[1],  x0 * t[0]));
                float S01 = fmaf(x2, t[5],  fmaf(x1, t[4],  x0 * t[3]));
                float S02 = fmaf(x2, t[8],  fmaf(x1, t[7],  x0 * t[6]));
                float S10 = fmaf(x2, t[11], fmaf(x1, t[10], x0 * t[9]));
                float S11 = fmaf(x2, t[14], fmaf(x1, t[13], x0 * t[12]));
                float S12 = fmaf(x2, t[17], fmaf(x1, t[16], x0 * t[15]));
                float S20 = fmaf(x2, t[20], fmaf(x1, t[19], x0 * t[18]));
                float S21 = fmaf(x2, t[23], fmaf(x1, t[22], x0 * t[21]));
                float S22 = fmaf(x2, t[26], fmaf(x1, t[25], x0 * t[24]));
                if (seg == 0) {
                    float a = P[0], b = P[1], cc = P[2];
                    P[0] = fmaf(cc, S20, fmaf(b, S10, fmaf(a, S00, a)));
                    P[1] = fmaf(cc, S21, fmaf(b, S11, fmaf(a, S01, b)));
                    P[2] = fmaf(cc, S22, fmaf(b, S12, fmaf(a, S02, cc)));
                } else {
                    #pragma unroll
                    for (int i = 0; i < 3; i++) {
                        float a = P[i*3+0], b = P[i*3+1], cc = P[i*3+2];
                        P[i*3+0] = fmaf(cc, S20, fmaf(b, S10, fmaf(a, S00, a)));
                        P[i*3+1] = fmaf(cc, S21, fmaf(b, S11, fmaf(a, S01, b)));
                        P[i*3+2] = fmaf(cc, S22, fmaf(b, S12, fmaf(a, S02, cc)));
                    }
                }
            } else {
                float M00 = fmaf(x2, t[2],  fmaf(x1, t[1],  fmaf(x0, t[0],  Bq[0])));
                float M01 = fmaf(x2, t[5],  fmaf(x1, t[4],  fmaf(x0, t[3],  Bq[1])));
                float M02 = fmaf(x2, t[8],  fmaf(x1, t[7],  fmaf(x0, t[6],  Bq[2])));
                float M10 = fmaf(x2, t[11], fmaf(x1, t[10], fmaf(x0, t[9],  Bq[3])));
                float M11 = fmaf(x2, t[14], fmaf(x1, t[13], fmaf(x0, t[12], Bq[4])));
                float M12 = fmaf(x2, t[17], fmaf(x1, t[16], fmaf(x0, t[15], Bq[5])));
                float M20 = fmaf(x2, t[20], fmaf(x1, t[19], fmaf(x0, t[18], Bq[6])));
                float M21 = fmaf(x2, t[23], fmaf(x1, t[22], fmaf(x0, t[21], Bq[7])));
                float M22 = fmaf(x2, t[26], fmaf(x1, t[25], fmaf(x0, t[24], Bq[8])));
                if (seg == 0) {
                    float a = P[0], b = P[1], cc = P[2];
                    P[0] = fmaf(cc, M20, fmaf(b, M10, a * M00));
                    P[1] = fmaf(cc, M21, fmaf(b, M11, a * M01));
                    P[2] = fmaf(cc, M22, fmaf(b, M12, a * M02));
                } else {
                    #pragma unroll
                    for (int i = 0; i < 3; i++) {
                        float a = P[i*3+0], b = P[i*3+1], cc = P[i*3+2];
                        P[i*3+0] = fmaf(cc, M20, fmaf(b, M10, a * M00));
                        P[i*3+1] = fmaf(cc, M21, fmaf(b, M11, a * M01));
                        P[i*3+2] = fmaf(cc, M22, fmaf(b, M12, a * M02));
                    }
                }
            }
        }

        // Stage chunk c+2 into buffer (c+2)%3. Its previous occupant (chunk
        // c-1) finished being read before this iteration's top barrier.
        if (c + 2 < NCH)
            stage_chunk(samples, base00 + (c + 2) * (CH * 3),
                        sbase + (uint32_t)(((c + 2) % NBUF) * CHUNKB), tid);
    }

    const int ge = e0 + tid;
    if (seg == 0) {
        g_vec[0 * NELEM + ge] = P[0];
        g_vec[1 * NELEM + ge] = P[1];
        g_vec[2 * NELEM + ge] = P[2];
    } else {
        #pragma unroll
        for (int j = 0; j < 9; j++)
            g_mat[((seg - 1) * 9 + j) * NELEM + ge] = P[j];
    }
}

__global__ void __launch_bounds__(BT)
mps_combine_kernel(float* __restrict__ out)
{
    const int e = blockIdx.x * BT + threadIdx.x;
    float r0 = g_vec[0 * NELEM + e];
    float r1 = g_vec[1 * NELEM + e];
    float r2 = g_vec[2 * NELEM + e];
    #pragma unroll
    for (int s = 0; s < 3; s++) {
        const float* m = g_mat + (size_t)(s * 9) * NELEM + e;
        float m0 = m[0*NELEM], m1 = m[1*NELEM], m2 = m[2*NELEM];
        float m3 = m[3*NELEM], m4 = m[4*NELEM], m5 = m[5*NELEM];
        float m6 = m[6*NELEM], m7 = m[7*NELEM], m8 = m[8*NELEM];
        float n0 = fmaf(r2, m6, fmaf(r1, m3, r0 * m0));
        float n1 = fmaf(r2, m7, fmaf(r1, m4, r0 * m1));
        float n2 = fmaf(r2, m8, fmaf(r1, m5, r0 * m2));
        r0 = n0; r1 = n1; r2 = n2;
    }
    float* o = out + (size_t)e * 3;
    o[0] = r0; o[1] = r1; o[2] = r2;
}

extern "C" void kernel_launch(void* const* d_in, const int* in_sizes, int n_in,
                              void* d_out, int out_size) {
    (void)in_sizes; (void)n_in; (void)out_size;
    const float* samples = (const float*)d_in[0];
    const float* tensors = (const float*)d_in[1];
    const float* bias    = (const float*)d_in[2];
    float* out = (float*)d_out;

    cudaFuncSetAttribute(mps_partial_kernel,
                         cudaFuncAttributeMaxDynamicSharedMemorySize, SMEM_BYTES);
    mps_partial_kernel<<<NBLK, BT, SMEM_BYTES>>>(samples, tensors, bias);
    mps_combine_kernel<<<NELEM / BT, BT>>>(out);
}